// round 6
// baseline (speedup 1.0000x reference)
#include <cuda_runtime.h>
#include <cuda_bf16.h>
#include <cstdint>

// Problem constants
#define Bn  256
#define Cn  2048
#define HW  196
#define En  16
#define An  3000

// GEMM tiling
#define BT  16      // samples per tile
#define AT  256     // answers per tile
#define KC  32      // K chunk

// Scratch (no cudaMalloc allowed)
__device__ float g_attended[Bn * Cn];      // 2 MB
__device__ int   g_lists[En * Bn];
__device__ int   g_counts[En];

// ---------------------------------------------------------------------------
// Kernel 0: dtype-robust deterministic grouping of samples by expert.
// inst may be int32 or int64 (JAX silently downcasts int64 -> int32 without
// x64). Detect: read first Bn int32 words; if every odd-indexed word is zero,
// the buffer is little-endian int64 (values 0..15 -> high word 0).
// ---------------------------------------------------------------------------
__global__ void group_kernel(const int* __restrict__ inst_raw) {
    __shared__ int s_lo[Bn];
    __shared__ int s_inst[Bn];
    __shared__ int s_is64;
    int tid = threadIdx.x;

    s_lo[tid] = inst_raw[tid];               // safe for both dtypes
    __syncthreads();

    if (tid == 0) {
        int all0 = 1;
        for (int i = 1; i < Bn; i += 2)
            if (s_lo[i] != 0) { all0 = 0; break; }
        s_is64 = all0;
    }
    __syncthreads();

    if (s_is64) {
        if (tid < Bn / 2) s_inst[tid] = s_lo[2 * tid];
        else              s_inst[tid] = inst_raw[2 * tid];  // words 256..510 < 512
    } else {
        s_inst[tid] = s_lo[tid];
    }
    __syncthreads();

    if (tid < En) {
        int e = tid;
        int cnt = 0;
        for (int b = 0; b < Bn; b++) {
            if (s_inst[b] == e) g_lists[e * Bn + (cnt++)] = b;
        }
        g_counts[e] = cnt;
    }
}

// ---------------------------------------------------------------------------
// Kernel 1: masked average pooling.
// grid (Bn, 8), block 256. Each warp handles 32 channels; mask row in smem.
// ---------------------------------------------------------------------------
__global__ __launch_bounds__(256) void pool_kernel(const float* __restrict__ mask,
                                                   const float* __restrict__ feat) {
    int b = blockIdx.x;
    __shared__ float4 s_m4[50];           // 196 floats + pad
    __shared__ float  s_inv;
    float* s_m = (float*)s_m4;

    int tid = threadIdx.x;
    if (tid < HW) s_m[tid] = mask[b * HW + tid] + 1e-10f;
    if (tid >= HW && tid < 200) s_m[tid] = 0.0f;
    __syncthreads();

    if (tid < 32) {
        float s = 0.0f;
        for (int i = tid; i < HW; i += 32) s += s_m[i];
        #pragma unroll
        for (int o = 16; o; o >>= 1) s += __shfl_down_sync(0xffffffffu, s, o);
        if (tid == 0) s_inv = 1.0f / s;
    }
    __syncthreads();

    int lane = tid & 31;
    int warp = tid >> 5;
    int c0 = blockIdx.y * 256 + warp * 32;
    float inv = s_inv;

    for (int cc = 0; cc < 32; cc++) {
        int c = c0 + cc;
        const float4* row4 =
            reinterpret_cast<const float4*>(feat + ((size_t)b * Cn + c) * HW);
        float s = 0.0f;
        #pragma unroll
        for (int i = lane; i < 49; i += 32) {   // 49 float4 = 196 floats
            float4 v = row4[i];
            float4 m = s_m4[i];
            s += v.x * m.x + v.y * m.y + v.z * m.z + v.w * m.w;
        }
        #pragma unroll
        for (int o = 16; o; o >>= 1) s += __shfl_down_sync(0xffffffffu, s, o);
        if (lane == 0) g_attended[b * Cn + c] = s * inv;
    }
}

// ---------------------------------------------------------------------------
// Kernel 2: per-expert grouped GEMM  out[b,a] = attended[b,:]·W[e,a,:] + bias
// grid (ceil(A/AT)=12, E=16), block 256.
// Tile: [BT=16 b  x  AT=256 a], each thread 2b x 8a, packed f32x2 FMAs.
// W staged in smem as [c][a] with XOR swizzle (conflict-free both directions).
// ---------------------------------------------------------------------------
__device__ __forceinline__ unsigned long long pack2(float v) {
    union { float2 f; unsigned long long u; } c;
    c.f = make_float2(v, v);
    return c.u;
}
__device__ __forceinline__ void fma2(unsigned long long& d,
                                     unsigned long long a,
                                     unsigned long long b) {
    asm("fma.rn.f32x2 %0, %1, %2, %0;" : "+l"(d) : "l"(a), "l"(b));
}

__global__ __launch_bounds__(256) void gemm_kernel(const float* __restrict__ Wmat,
                                                   const float* __restrict__ bias,
                                                   float* __restrict__ out) {
    const int e = blockIdx.y;
    const int n = g_counts[e];
    if (n == 0) return;
    const int a0 = blockIdx.x * AT;

    const int tid  = threadIdx.x;
    const int lane = tid & 31;
    const int warp = tid >> 5;          // 0..7 : handles b rows {2w, 2w+1}
    const int tx   = lane;              // handles a cols {tx*4..+3, 128+tx*4..+3}

    __shared__ float sW[KC * AT];       // 32 KB, swizzled [c][a]
    __shared__ float sA[KC][BT + 2];    // 32 x 18
    __shared__ int   s_list[Bn];

    s_list[tid] = (tid < n) ? g_lists[e * Bn + tid] : 0;
    __syncthreads();

    // W-loader lane mapping: iteration i loads a_loc = i*32 + warp*4 + (lane>>3),
    // 4 consecutive c's at c4*4.  Coalesced 128B per a-row.
    const int aw = warp * 4 + (lane >> 3);
    const int c4 = lane & 7;
    const int a3 = lane >> 3;           // a_loc & 3

    for (int bt = 0; bt < n; bt += BT) {
        unsigned long long acc[2][4];
        #pragma unroll
        for (int r = 0; r < 2; r++)
            #pragma unroll
            for (int p = 0; p < 4; p++) acc[r][p] = 0ull;

        float4 wreg[8];
        float4 areg = make_float4(0.f, 0.f, 0.f, 0.f);

        // ---- preload chunk 0 ----
        #pragma unroll
        for (int i = 0; i < 8; i++) {
            int a_loc = i * 32 + aw;
            int ag = a0 + a_loc;
            if (ag < An)
                wreg[i] = *reinterpret_cast<const float4*>(
                    Wmat + ((size_t)(e * An + ag)) * Cn + c4 * 4);
            else
                wreg[i] = make_float4(0.f, 0.f, 0.f, 0.f);
        }
        if (tid < 128) {
            int bb = tid >> 3, cc = tid & 7;
            int idx = bt + bb;
            if (idx < n)
                areg = *reinterpret_cast<const float4*>(
                    &g_attended[(size_t)s_list[idx] * Cn + cc * 4]);
            else
                areg = make_float4(0.f, 0.f, 0.f, 0.f);
        }

        for (int k0 = 0; k0 < Cn; k0 += KC) {
            __syncthreads();
            // ---- store staged regs into smem (transpose, swizzled) ----
            #pragma unroll
            for (int i = 0; i < 8; i++) {
                int l = i * 8 + warp;   // logical f4-granule (lane-invariant)
                const float* wf = (const float*)&wreg[i];
                #pragma unroll
                for (int j = 0; j < 4; j++) {
                    int r = (j << 3) | c4;        // permuted row of c = c4*4+j
                    int p = l ^ c4;               // XOR swizzle (r&7 == c4)
                    sW[r * AT + p * 4 + a3] = wf[j];
                }
            }
            if (tid < 128) {
                int bb = tid >> 3, cc = tid & 7;
                const float* af = (const float*)&areg;
                #pragma unroll
                for (int j = 0; j < 4; j++) sA[cc * 4 + j][bb] = af[j];
            }
            __syncthreads();

            // ---- prefetch next chunk (LDGs in flight while computing) ----
            int kn = k0 + KC;
            if (kn < Cn) {
                #pragma unroll
                for (int i = 0; i < 8; i++) {
                    int a_loc = i * 32 + aw;
                    int ag = a0 + a_loc;
                    if (ag < An)
                        wreg[i] = *reinterpret_cast<const float4*>(
                            Wmat + ((size_t)(e * An + ag)) * Cn + kn + c4 * 4);
                    else
                        wreg[i] = make_float4(0.f, 0.f, 0.f, 0.f);
                }
                if (tid < 128) {
                    int bb = tid >> 3, cc = tid & 7;
                    int idx = bt + bb;
                    if (idx < n)
                        areg = *reinterpret_cast<const float4*>(
                            &g_attended[(size_t)s_list[idx] * Cn + kn + cc * 4]);
                }
            }

            // ---- compute ----
            #pragma unroll
            for (int kk = 0; kk < KC; kk++) {
                int r  = ((kk & 3) << 3) | (kk >> 2);  // permuted row
                int xr = kk >> 2;                      // = r & 7
                union { float4 f; unsigned long long u[2]; } w0, w1;
                w0.f = *reinterpret_cast<const float4*>(
                    &sW[r * AT + (tx ^ xr) * 4]);
                w1.f = *reinterpret_cast<const float4*>(
                    &sW[r * AT + (32 + (tx ^ xr)) * 4]);
                float2 av = *reinterpret_cast<const float2*>(&sA[kk][warp * 2]);
                unsigned long long pa0 = pack2(av.x);
                unsigned long long pa1 = pack2(av.y);
                fma2(acc[0][0], pa0, w0.u[0]);
                fma2(acc[0][1], pa0, w0.u[1]);
                fma2(acc[0][2], pa0, w1.u[0]);
                fma2(acc[0][3], pa0, w1.u[1]);
                fma2(acc[1][0], pa1, w0.u[0]);
                fma2(acc[1][1], pa1, w0.u[1]);
                fma2(acc[1][2], pa1, w1.u[0]);
                fma2(acc[1][3], pa1, w1.u[1]);
            }
        }

        // ---- epilogue ----
        #pragma unroll
        for (int r = 0; r < 2; r++) {
            int bb = warp * 2 + r;
            if (bt + bb < n) {
                int bg = s_list[bt + bb];
                size_t obase = (size_t)bg * An;
                const int rel[4] = { tx * 4, tx * 4 + 2,
                                     128 + tx * 4, 128 + tx * 4 + 2 };
                #pragma unroll
                for (int p = 0; p < 4; p++) {
                    union { unsigned long long u; float2 f; } cv;
                    cv.u = acc[r][p];
                    int ag = a0 + rel[p];
                    if (ag < An)
                        out[obase + ag] = cv.f.x + bias[e * An + ag];
                    if (ag + 1 < An)
                        out[obase + ag + 1] = cv.f.y + bias[e * An + ag + 1];
                }
            }
        }
    }
}

// ---------------------------------------------------------------------------
// kernel_launch: identify inputs BY ELEMENT COUNT (immune to metadata order).
//   mask     : 256*1*14*14   = 50176
//   features : 256*2048*196  = 102760448
//   W        : 16*3000*2048  = 98304000
//   b        : 16*3000       = 48000
//   inst     : 256
// ---------------------------------------------------------------------------
extern "C" void kernel_launch(void* const* d_in, const int* in_sizes, int n_in,
                              void* d_out, int out_size) {
    const float* mask = nullptr;
    const float* feat = nullptr;
    const float* Wmat = nullptr;
    const float* bias = nullptr;
    const int*   inst = nullptr;

    for (int i = 0; i < n_in; i++) {
        switch (in_sizes[i]) {
            case 50176:     mask = (const float*)d_in[i]; break;
            case 102760448: feat = (const float*)d_in[i]; break;
            case 98304000:  Wmat = (const float*)d_in[i]; break;
            case 48000:     bias = (const float*)d_in[i]; break;
            case 256:       inst = (const int*)  d_in[i]; break;
            default: break;
        }
    }
    float* outp = (float*)d_out;   // [B, A] float32

    group_kernel<<<1, Bn>>>(inst);
    pool_kernel<<<dim3(Bn, Cn / 256), 256>>>(mask, feat);
    gemm_kernel<<<dim3((An + AT - 1) / AT, En), 256>>>(Wmat, bias, outp);
}

// round 7
// speedup vs baseline: 2.1625x; 2.1625x over previous
#include <cuda_runtime.h>
#include <cuda_bf16.h>
#include <cstdint>

// Problem constants
#define Bn  256
#define Cn  2048
#define HW  196
#define En  16
#define An  3000

// GEMM tiling
#define BT  16      // samples per tile
#define AT  128     // answers per tile
#define KC  32      // K chunk

// Scratch (no cudaMalloc allowed)
__device__ float g_attended[Bn * Cn];      // 2 MB

// ---------------------------------------------------------------------------
// Kernel 1: masked average pooling. grid (Bn, 8), block 256.
// Each warp: 32 channels, processed 4 at a time (8 LDGs in flight,
// 4 overlapped butterfly reductions).
// ---------------------------------------------------------------------------
__global__ __launch_bounds__(256) void pool_kernel(const float* __restrict__ mask,
                                                   const float* __restrict__ feat) {
    int b = blockIdx.x;
    __shared__ float4 s_m4[50];           // 196 floats + pad
    __shared__ float  s_inv;
    float* s_m = (float*)s_m4;

    int tid = threadIdx.x;
    if (tid < HW) s_m[tid] = mask[b * HW + tid] + 1e-10f;
    if (tid >= HW && tid < 200) s_m[tid] = 0.0f;
    __syncthreads();

    if (tid < 32) {
        float s = 0.0f;
        for (int i = tid; i < HW; i += 32) s += s_m[i];
        #pragma unroll
        for (int o = 16; o; o >>= 1) s += __shfl_down_sync(0xffffffffu, s, o);
        if (tid == 0) s_inv = 1.0f / s;
    }
    __syncthreads();

    int lane = tid & 31;
    int warp = tid >> 5;
    int c0 = blockIdx.y * 256 + warp * 32;
    float inv = s_inv;

    for (int cc = 0; cc < 32; cc += 4) {
        int c = c0 + cc;
        const float4* r0 = reinterpret_cast<const float4*>(feat + ((size_t)b * Cn + c + 0) * HW);
        const float4* r1 = reinterpret_cast<const float4*>(feat + ((size_t)b * Cn + c + 1) * HW);
        const float4* r2 = reinterpret_cast<const float4*>(feat + ((size_t)b * Cn + c + 2) * HW);
        const float4* r3 = reinterpret_cast<const float4*>(feat + ((size_t)b * Cn + c + 3) * HW);
        float s0 = 0.f, s1 = 0.f, s2 = 0.f, s3 = 0.f;
        #pragma unroll
        for (int i = lane; i < 49; i += 32) {   // 49 float4 = 196 floats
            float4 m  = s_m4[i];
            float4 v0 = r0[i];
            float4 v1 = r1[i];
            float4 v2 = r2[i];
            float4 v3 = r3[i];
            s0 += v0.x * m.x + v0.y * m.y + v0.z * m.z + v0.w * m.w;
            s1 += v1.x * m.x + v1.y * m.y + v1.z * m.z + v1.w * m.w;
            s2 += v2.x * m.x + v2.y * m.y + v2.z * m.z + v2.w * m.w;
            s3 += v3.x * m.x + v3.y * m.y + v3.z * m.z + v3.w * m.w;
        }
        #pragma unroll
        for (int o = 16; o; o >>= 1) {          // 4 independent chains overlap
            s0 += __shfl_xor_sync(0xffffffffu, s0, o);
            s1 += __shfl_xor_sync(0xffffffffu, s1, o);
            s2 += __shfl_xor_sync(0xffffffffu, s2, o);
            s3 += __shfl_xor_sync(0xffffffffu, s3, o);
        }
        if (lane == 0) {
            *reinterpret_cast<float4*>(&g_attended[(size_t)b * Cn + c]) =
                make_float4(s0 * inv, s1 * inv, s2 * inv, s3 * inv);
        }
    }
}

// ---------------------------------------------------------------------------
// Kernel 2: single-wave grouped GEMM with fused deterministic grouping.
// grid (24 a-tiles, 16 experts, 2 bt-chunks), block 128 (4 warps).
// Tile [BT=16 b x AT=128 a]; warp w -> b rows 4w..4w+3 (A broadcast),
// lane tx -> a columns tx*4..tx*4+3.  Packed f32x2 FMAs.
// W staged in smem [c][a] with XOR swizzle (conflict-free stores AND reads).
// ---------------------------------------------------------------------------
typedef unsigned long long ull;

__device__ __forceinline__ ull pack2(float v) {
    union { float2 f; ull u; } c;
    c.f = make_float2(v, v);
    return c.u;
}
__device__ __forceinline__ void fma2(ull& d, ull a, ull b) {
    asm("fma.rn.f32x2 %0, %1, %2, %0;" : "+l"(d) : "l"(a), "l"(b));
}

__global__ __launch_bounds__(128) void gemm_kernel(const float* __restrict__ Wmat,
                                                   const float* __restrict__ bias,
                                                   const int* __restrict__ inst_raw,
                                                   float* __restrict__ out) {
    const int e  = blockIdx.y;
    const int a0 = blockIdx.x * AT;
    const int t  = threadIdx.x;
    const int l  = t & 31;
    const int w  = t >> 5;

    __shared__ float sW[KC * AT];        // 16 KB swizzled [c][a]
    __shared__ float sA[KC][20];         // [c][b], pad 20 (16B-aligned rows)
    __shared__ int   s_list[Bn];
    __shared__ int   s_wcnt[8];

    // ---- fused deterministic grouping (ballot + prefix) ----
    // dtype detect: int64 iff all odd int32 words of the first 256 are zero
    int oddw = inst_raw[2 * t + 1];
    int is64 = __syncthreads_and(oddw == 0);
    int b0 = t, b1 = t + 128;
    int i0 = is64 ? inst_raw[2 * b0] : inst_raw[b0];
    int i1 = is64 ? inst_raw[2 * b1] : inst_raw[b1];
    unsigned m0 = __ballot_sync(0xffffffffu, i0 == e);
    unsigned m1 = __ballot_sync(0xffffffffu, i1 == e);
    if (l == 0) { s_wcnt[w] = __popc(m0); s_wcnt[4 + w] = __popc(m1); }
    __syncthreads();
    int q0 = s_wcnt[0], q1 = s_wcnt[1], q2 = s_wcnt[2], q3 = s_wcnt[3];
    int q4 = s_wcnt[4], q5 = s_wcnt[5], q6 = s_wcnt[6], q7 = s_wcnt[7];
    int half = q0 + q1 + q2 + q3;
    int n    = half + q4 + q5 + q6 + q7;
    int base0 = (w > 0 ? q0 : 0) + (w > 1 ? q1 : 0) + (w > 2 ? q2 : 0);
    int base1 = half + (w > 0 ? q4 : 0) + (w > 1 ? q5 : 0) + (w > 2 ? q6 : 0);
    unsigned lmask = (1u << l) - 1u;
    if (i0 == e) s_list[base0 + __popc(m0 & lmask)] = b0;
    if (i1 == e) s_list[base1 + __popc(m1 & lmask)] = b1;
    __syncthreads();

    // loader lane mappings
    const int fr  = t & 7;       // f4 index within 32-c chunk (== xr at store)
    const int rr  = t >> 3;      // row-in-16 (0..15)
    const int gwu = t >> 5;      // uniform part of granule
    const int ca  = t & 31;      // A-loader: c within chunk
    const int bq  = t >> 5;      // A-loader: b quad

    const float* We = Wmat + (size_t)e * An * Cn;

    for (int bt = blockIdx.z * BT; bt < n; bt += 2 * BT) {
        ull acc[4][2];
        #pragma unroll
        for (int i = 0; i < 4; i++) { acc[i][0] = 0ull; acc[i][1] = 0ull; }

        float4 wreg[8];
        float  areg[4];

        // ---- preload chunk 0 ----
        #pragma unroll
        for (int i = 0; i < 8; i++) {
            int ag = a0 + i * 16 + rr;
            wreg[i] = (ag < An)
                ? *reinterpret_cast<const float4*>(We + (size_t)ag * Cn + fr * 4)
                : make_float4(0.f, 0.f, 0.f, 0.f);
        }
        #pragma unroll
        for (int r = 0; r < 4; r++) {
            int idx = bt + bq * 4 + r;
            areg[r] = (idx < n) ? g_attended[(size_t)s_list[idx] * Cn + ca] : 0.0f;
        }

        for (int k0 = 0; k0 < Cn; k0 += KC) {
            __syncthreads();
            // ---- store staged regs into smem ----
            #pragma unroll
            for (int i = 0; i < 8; i++) {
                int sg = ((i * 4 + gwu) ^ fr);        // swizzled granule slot
                int a3 = rr & 3;
                const float* f = (const float*)&wreg[i];
                #pragma unroll
                for (int j = 0; j < 4; j++) {
                    int r = (j << 3) | fr;            // permuted c-row
                    sW[r * AT + sg * 4 + a3] = f[j];
                }
            }
            *reinterpret_cast<float4*>(&sA[ca][bq * 4]) =
                make_float4(areg[0], areg[1], areg[2], areg[3]);
            __syncthreads();

            // ---- prefetch next chunk ----
            int kn = k0 + KC;
            if (kn < Cn) {
                #pragma unroll
                for (int i = 0; i < 8; i++) {
                    int ag = a0 + i * 16 + rr;
                    wreg[i] = (ag < An)
                        ? *reinterpret_cast<const float4*>(We + (size_t)ag * Cn + kn + fr * 4)
                        : make_float4(0.f, 0.f, 0.f, 0.f);
                }
                #pragma unroll
                for (int r = 0; r < 4; r++) {
                    int idx = bt + bq * 4 + r;
                    areg[r] = (idx < n) ? g_attended[(size_t)s_list[idx] * Cn + kn + ca] : 0.0f;
                }
            }

            // ---- compute ----
            #pragma unroll
            for (int kk = 0; kk < KC; kk++) {
                int r  = ((kk & 3) << 3) | (kk >> 2); // permuted c-row
                int xr = kk >> 2;
                union { float4 f; ull u[2]; } wv;
                wv.f = *reinterpret_cast<const float4*>(&sW[r * AT + (l ^ xr) * 4]);
                float4 av = *reinterpret_cast<const float4*>(&sA[kk][w * 4]);
                ull pa0 = pack2(av.x), pa1 = pack2(av.y);
                ull pa2 = pack2(av.z), pa3 = pack2(av.w);
                fma2(acc[0][0], pa0, wv.u[0]); fma2(acc[0][1], pa0, wv.u[1]);
                fma2(acc[1][0], pa1, wv.u[0]); fma2(acc[1][1], pa1, wv.u[1]);
                fma2(acc[2][0], pa2, wv.u[0]); fma2(acc[2][1], pa2, wv.u[1]);
                fma2(acc[3][0], pa3, wv.u[0]); fma2(acc[3][1], pa3, wv.u[1]);
            }
        }

        // ---- epilogue (An % 4 == 0 -> always full float4 when in range) ----
        int abase = a0 + l * 4;
        if (abase < An) {
            float4 b4 = *reinterpret_cast<const float4*>(&bias[(size_t)e * An + abase]);
            #pragma unroll
            for (int i = 0; i < 4; i++) {
                int idx = bt + w * 4 + i;
                if (idx < n) {
                    int bg = s_list[idx];
                    union { ull u; float2 f; } lo, hi;
                    lo.u = acc[i][0]; hi.u = acc[i][1];
                    float4 o = make_float4(lo.f.x + b4.x, lo.f.y + b4.y,
                                           hi.f.x + b4.z, hi.f.y + b4.w);
                    *reinterpret_cast<float4*>(&out[(size_t)bg * An + abase]) = o;
                }
            }
        }
    }
}

// ---------------------------------------------------------------------------
// kernel_launch: identify inputs BY ELEMENT COUNT (immune to metadata order).
//   mask 50176 | features 102760448 | W 98304000 | b 48000 | inst 256
// ---------------------------------------------------------------------------
extern "C" void kernel_launch(void* const* d_in, const int* in_sizes, int n_in,
                              void* d_out, int out_size) {
    const float* mask = nullptr;
    const float* feat = nullptr;
    const float* Wmat = nullptr;
    const float* bias = nullptr;
    const int*   inst = nullptr;

    for (int i = 0; i < n_in; i++) {
        switch (in_sizes[i]) {
            case 50176:     mask = (const float*)d_in[i]; break;
            case 102760448: feat = (const float*)d_in[i]; break;
            case 98304000:  Wmat = (const float*)d_in[i]; break;
            case 48000:     bias = (const float*)d_in[i]; break;
            case 256:       inst = (const int*)  d_in[i]; break;
            default: break;
        }
    }
    float* outp = (float*)d_out;   // [B, A] float32

    pool_kernel<<<dim3(Bn, Cn / 256), 256>>>(mask, feat);
    gemm_kernel<<<dim3((An + AT - 1) / AT, En, 2), 128>>>(Wmat, bias, inst, outp);
}